// round 6
// baseline (speedup 1.0000x reference)
#include <cuda_runtime.h>
#include <cuda_bf16.h>

// NMU forward: y[b,o] = prod_d ( M_hat[d,o]*x[b,d] + (1 - M_hat[d,o]) )
//            = prod_d ( M_hat[d,o]*(x[b,d]-1) + 1 )
// B=16384, D=256, O=32, fp32.
//
// R6: O-dim packed into f32x2.
//  - block = 512 thr (16 warps), tile = 16 rows; warp w owns d in [16w,16w+16).
//  - lane: lp = lane&15 owns o-pair (2lp, 2lp+1); half-warp h = lane>>4
//    processes row 2*rp + h  -> each LDS.128 serves two rows (one per half),
//    16 useful B per wavefront (2x better than full-warp broadcast).
//  - x scalar duplicated into f32x2 via mov.b64 {r,r} (idle ALU pipe).
//  - m packed along o: m2[d] = (m[d][2lp], m[d][2lp+1]), 32 regs.
//  - partials stay packed; 16-way packed-mul2 tree epilogue, STG.64 out.

#define NMU_D   256
#define NMU_O   32
#define NMU_R   16        // rows per block tile
#define NMU_NW  16        // warps per block
#define NMU_DPW 16        // d's per warp chunk

__device__ __forceinline__ unsigned long long f2_fma(unsigned long long a,
                                                     unsigned long long b,
                                                     unsigned long long c) {
    unsigned long long d;
    asm("fma.rn.f32x2 %0, %1, %2, %3;" : "=l"(d) : "l"(a), "l"(b), "l"(c));
    return d;
}
__device__ __forceinline__ unsigned long long f2_mul(unsigned long long a,
                                                     unsigned long long b) {
    unsigned long long d;
    asm("mul.rn.f32x2 %0, %1, %2;" : "=l"(d) : "l"(a), "l"(b));
    return d;
}
__device__ __forceinline__ unsigned long long pack2(float a, float b) {
    unsigned long long d;
    asm("mov.b64 %0, {%1, %2};" : "=l"(d)
        : "r"(__float_as_uint(a)), "r"(__float_as_uint(b)));
    return d;
}
// duplicate one scalar into both f32x2 lanes (ALU pipe)
__device__ __forceinline__ unsigned long long dup2(float v) {
    unsigned long long d;
    unsigned u = __float_as_uint(v);
    asm("mov.b64 %0, {%1, %1};" : "=l"(d) : "r"(u));
    return d;
}

#define NMU_ONE2 0x3f8000003f800000ULL

__global__ void __launch_bounds__(512, 2)
nmu_kernel(const float* __restrict__ x, const float* __restrict__ M,
           float* __restrict__ out) {
    __shared__ float us[NMU_R * NMU_D];                         // 16 KB (x-1)
    __shared__ unsigned long long pw[NMU_NW * NMU_R * 16];      // 32 KB partials

    const int tid  = threadIdx.x;
    const int warp = tid >> 5;
    const int lane = tid & 31;
    const int h    = lane >> 4;          // half-warp -> row parity
    const int lp   = lane & 15;          // o-pair index
    const int d0   = warp * NMU_DPW;
    const int b0   = blockIdx.x * NMU_R;

    // --- weights: 16 packed o-pairs (one 128B line per LDG, L1/L2-hot) ---
    unsigned long long m2[16];
    #pragma unroll
    for (int k = 0; k < 16; k++) {
        float2 mm = __ldg((const float2*)(M + (size_t)(d0 + k) * NMU_O) + lp);
        m2[k] = pack2(__saturatef(mm.x), __saturatef(mm.y));
    }

    // --- stage u = x - 1 (coalesced float4, subtract folded in) ---
    {
        const float4* __restrict__ xg = (const float4*)(x + (size_t)b0 * NMU_D);
        float4* us4 = (float4*)us;
        #pragma unroll
        for (int i = 0; i < (NMU_R * NMU_D / 4) / 512; i++) {   // 2 iters
            float4 v = xg[tid + i * 512];
            v.x -= 1.0f; v.y -= 1.0f; v.z -= 1.0f; v.w -= 1.0f;
            us4[tid + i * 512] = v;
        }
    }
    __syncthreads();

    // --- hot loop: 8 row-pair iters; half-warp h handles row 2*rp+h ---
    #pragma unroll 2
    for (int rp = 0; rp < NMU_R / 2; rp++) {
        const int r = 2 * rp + h;
        const float4* __restrict__ ur = (const float4*)(us + r * NMU_D + d0);

        unsigned long long p, q, t;
        // d0 .. d0+7
        {
            float4 a = ur[0], b = ur[1];
            t = f2_fma(m2[0], dup2(a.x), NMU_ONE2);  p = t;
            t = f2_fma(m2[1], dup2(a.y), NMU_ONE2);  q = t;
            t = f2_fma(m2[2], dup2(a.z), NMU_ONE2);  p = f2_mul(p, t);
            t = f2_fma(m2[3], dup2(a.w), NMU_ONE2);  q = f2_mul(q, t);
            t = f2_fma(m2[4], dup2(b.x), NMU_ONE2);  p = f2_mul(p, t);
            t = f2_fma(m2[5], dup2(b.y), NMU_ONE2);  q = f2_mul(q, t);
            t = f2_fma(m2[6], dup2(b.z), NMU_ONE2);  p = f2_mul(p, t);
            t = f2_fma(m2[7], dup2(b.w), NMU_ONE2);  q = f2_mul(q, t);
        }
        // d0+8 .. d0+15
        {
            float4 c = ur[2], e = ur[3];
            t = f2_fma(m2[ 8], dup2(c.x), NMU_ONE2);  p = f2_mul(p, t);
            t = f2_fma(m2[ 9], dup2(c.y), NMU_ONE2);  q = f2_mul(q, t);
            t = f2_fma(m2[10], dup2(c.z), NMU_ONE2);  p = f2_mul(p, t);
            t = f2_fma(m2[11], dup2(c.w), NMU_ONE2);  q = f2_mul(q, t);
            t = f2_fma(m2[12], dup2(e.x), NMU_ONE2);  p = f2_mul(p, t);
            t = f2_fma(m2[13], dup2(e.y), NMU_ONE2);  q = f2_mul(q, t);
            t = f2_fma(m2[14], dup2(e.z), NMU_ONE2);  p = f2_mul(p, t);
            t = f2_fma(m2[15], dup2(e.w), NMU_ONE2);  q = f2_mul(q, t);
        }

        // packed chunk-partial for o-pair (2lp, 2lp+1): no unpack needed
        pw[(warp * NMU_R + r) * 16 + lp] = f2_mul(p, q);   // STS.64
    }
    __syncthreads();

    // --- epilogue: 256 cells (16 rows x 16 o-pairs), packed mul2 tree ---
    if (tid < NMU_R * 16) {
        const int r  = tid >> 4;
        const int jp = tid & 15;
        const unsigned long long* pp = pw + r * 16 + jp;
        const int S = NMU_R * 16;                 // stride between warp slabs
        unsigned long long v[8];
        #pragma unroll
        for (int w = 0; w < 8; w++)
            v[w] = f2_mul(pp[(2 * w) * S], pp[(2 * w + 1) * S]);
        unsigned long long a0 = f2_mul(v[0], v[1]);
        unsigned long long a1 = f2_mul(v[2], v[3]);
        unsigned long long a2 = f2_mul(v[4], v[5]);
        unsigned long long a3 = f2_mul(v[6], v[7]);
        unsigned long long pr = f2_mul(f2_mul(a0, a1), f2_mul(a2, a3));

        float2 res;
        res.x = __uint_as_float((unsigned)(pr & 0xffffffffULL));
        res.y = __uint_as_float((unsigned)(pr >> 32));
        ((float2*)(out + (size_t)(b0 + r) * NMU_O))[jp] = res;   // STG.64
    }
}

extern "C" void kernel_launch(void* const* d_in, const int* in_sizes, int n_in,
                              void* d_out, int out_size) {
    const float* x = (const float*)d_in[0];   // [16384, 256]
    const float* M = (const float*)d_in[1];   // [256, 32]
    float* out = (float*)d_out;               // [16384, 32]

    const int B = in_sizes[0] / NMU_D;        // 16384

    nmu_kernel<<<B / NMU_R, 512>>>(x, M, out);
}